// round 2
// baseline (speedup 1.0000x reference)
#include <cuda_runtime.h>
#include <math.h>

// Problem constants
#define KK 4
#define BB 2
#define SS 1024
#define DD 1024
#define NROWS (KK*BB*SS)      // 8192 rows of length D
#define BSROWS (BB*SS)        // 2048
#define BSD (BB*SS*DD)        // 2,097,152
#define NBSD (KK*BSD)         // 8,388,608

// Scratch (allocation-free: device globals)
__device__ float g_partial[NROWS * 24];   // per-row partial reductions
__device__ float g_inv[NROWS];            // per-row rsqrt(mean(x^2)+eps)
__device__ float g_maps[24];              // [0..15] res_map[n*4+m], [16..19] pre, [20..23] post

// ---------------------------------------------------------------------------
// Kernel 1: per-row RMS norm + the big alpha reductions.
// One block = one (n,b,s) row. All alpha accesses are contiguous streaming.
// ---------------------------------------------------------------------------
__global__ __launch_bounds__(256) void k_reduce(
    const float* __restrict__ x,
    const float* __restrict__ w,
    const float* __restrict__ ra,   // res_alpha  [row][D][16]
    const float* __restrict__ pa,   // pre_alpha  [row][D][4]
    const float* __restrict__ qa)   // post_alpha [row][D][4]
{
    __shared__ float xn_sh[DD];
    __shared__ float ssw[8];
    __shared__ float red[8 * 24];

    const int row = blockIdx.x;
    const int t   = threadIdx.x;
    const int wid = t >> 5;
    const int ln  = t & 31;

    // ---- RMS norm: each thread owns 4 consecutive d's ----
    const float4* x4 = reinterpret_cast<const float4*>(x) + (size_t)row * (DD / 4);
    float4 xv = x4[t];
    float ss = xv.x*xv.x + xv.y*xv.y + xv.z*xv.z + xv.w*xv.w;
    #pragma unroll
    for (int o = 16; o; o >>= 1) ss += __shfl_xor_sync(0xffffffffu, ss, o);
    if (ln == 0) ssw[wid] = ss;
    __syncthreads();
    float tot = ssw[0] + ssw[1] + ssw[2] + ssw[3] + ssw[4] + ssw[5] + ssw[6] + ssw[7];
    const float inv = rsqrtf(tot * (1.0f / (float)DD) + 1e-6f);
    if (t == 0) g_inv[row] = inv;

    float4 wv = reinterpret_cast<const float4*>(w)[t];
    float4 xnv;
    xnv.x = xv.x * inv * wv.x;
    xnv.y = xv.y * inv * wv.y;
    xnv.z = xv.z * inv * wv.z;
    xnv.w = xv.w * inv * wv.w;
    reinterpret_cast<float4*>(xn_sh)[t] = xnv;
    __syncthreads();

    // ---- res_alpha: row is [D][16] = 16384 floats = 4096 float4s ----
    // float4 index j covers d = j>>2, m = (j&3)*4 .. +3 ; j&3 == t&3 (constant per thread)
    const float4* ra4 = reinterpret_cast<const float4*>(ra) + (size_t)row * (DD * 16 / 4);
    float4 accr = make_float4(0.f, 0.f, 0.f, 0.f);
    #pragma unroll
    for (int i = 0; i < 16; i++) {
        const int j = i * 256 + t;
        float4 v = ra4[j];
        float xs = xn_sh[j >> 2];
        accr.x += xs * v.x; accr.y += xs * v.y; accr.z += xs * v.z; accr.w += xs * v.w;
    }

    // ---- pre_alpha: row is [D][4] = 1024 float4s; j covers d=j, m=0..3 ----
    const float4* pa4 = reinterpret_cast<const float4*>(pa) + (size_t)row * DD;
    const float4* qa4 = reinterpret_cast<const float4*>(qa) + (size_t)row * DD;
    float4 accp = make_float4(0.f, 0.f, 0.f, 0.f);
    float4 accq = make_float4(0.f, 0.f, 0.f, 0.f);
    #pragma unroll
    for (int i = 0; i < 4; i++) {
        const int j = i * 256 + t;
        float xs = xn_sh[j];
        float4 v = pa4[j];
        accp.x += xs * v.x; accp.y += xs * v.y; accp.z += xs * v.z; accp.w += xs * v.w;
        float4 u = qa4[j];
        accq.x += xs * u.x; accq.y += xs * u.y; accq.z += xs * u.z; accq.w += xs * u.w;
    }

    // ---- block reductions ----
    // res: sum over lanes with same (t&3): xor over offsets 16, 8, 4
    #pragma unroll
    for (int o = 16; o >= 4; o >>= 1) {
        accr.x += __shfl_xor_sync(0xffffffffu, accr.x, o);
        accr.y += __shfl_xor_sync(0xffffffffu, accr.y, o);
        accr.z += __shfl_xor_sync(0xffffffffu, accr.z, o);
        accr.w += __shfl_xor_sync(0xffffffffu, accr.w, o);
    }
    // pre/post: full warp reduce
    #pragma unroll
    for (int o = 16; o; o >>= 1) {
        accp.x += __shfl_xor_sync(0xffffffffu, accp.x, o);
        accp.y += __shfl_xor_sync(0xffffffffu, accp.y, o);
        accp.z += __shfl_xor_sync(0xffffffffu, accp.z, o);
        accp.w += __shfl_xor_sync(0xffffffffu, accp.w, o);
        accq.x += __shfl_xor_sync(0xffffffffu, accq.x, o);
        accq.y += __shfl_xor_sync(0xffffffffu, accq.y, o);
        accq.z += __shfl_xor_sync(0xffffffffu, accq.z, o);
        accq.w += __shfl_xor_sync(0xffffffffu, accq.w, o);
    }

    if (ln < 4) {   // lane ln holds res group g=ln -> m = ln*4 + c
        red[wid * 24 + ln * 4 + 0] = accr.x;
        red[wid * 24 + ln * 4 + 1] = accr.y;
        red[wid * 24 + ln * 4 + 2] = accr.z;
        red[wid * 24 + ln * 4 + 3] = accr.w;
    }
    if (ln == 0) {
        red[wid * 24 + 16] = accp.x; red[wid * 24 + 17] = accp.y;
        red[wid * 24 + 18] = accp.z; red[wid * 24 + 19] = accp.w;
        red[wid * 24 + 20] = accq.x; red[wid * 24 + 21] = accq.y;
        red[wid * 24 + 22] = accq.z; red[wid * 24 + 23] = accq.w;
    }
    __syncthreads();
    if (t < 24) {
        float s = 0.f;
        #pragma unroll
        for (int wv_ = 0; wv_ < 8; wv_++) s += red[wv_ * 24 + t];
        g_partial[(size_t)row * 24 + t] = s;
    }
}

// ---------------------------------------------------------------------------
// Kernel 2: reduce partials -> h[24]; sigmoid mappings + 4x4 Sinkhorn.
// ---------------------------------------------------------------------------
__device__ __forceinline__ float lse4(float a0, float a1, float a2, float a3) {
    float m = fmaxf(fmaxf(a0, a1), fmaxf(a2, a3));
    return m + logf(expf(a0 - m) + expf(a1 - m) + expf(a2 - m) + expf(a3 - m));
}

__global__ __launch_bounds__(256) void k_final(
    const float* __restrict__ rb,   // res_beta  (K,)
    const float* __restrict__ pb,   // pre_beta  (K,)
    const float* __restrict__ qb)   // post_beta (K,)
{
    const int t   = threadIdx.x;
    const int wid = t >> 5;
    const int ln  = t & 31;

    float acc[24];
    #pragma unroll
    for (int v = 0; v < 24; v++) acc[v] = 0.f;
    for (int r = t; r < NROWS; r += 256) {
        const float* p = g_partial + (size_t)r * 24;
        #pragma unroll
        for (int v = 0; v < 24; v++) acc[v] += p[v];
    }
    #pragma unroll
    for (int v = 0; v < 24; v++) {
        #pragma unroll
        for (int o = 16; o; o >>= 1) acc[v] += __shfl_xor_sync(0xffffffffu, acc[v], o);
    }
    __shared__ float sh[8][24];
    __shared__ float h[24];
    if (ln == 0) {
        #pragma unroll
        for (int v = 0; v < 24; v++) sh[wid][v] = acc[v];
    }
    __syncthreads();
    if (t < 24) {
        float s = 0.f;
        #pragma unroll
        for (int wv_ = 0; wv_ < 8; wv_++) s += sh[wv_][t];
        h[t] = s;
    }
    __syncthreads();

    if (t == 0) {
        // pre_mapping = sigmoid(1e-4*h_pre + pre_beta)
        // post_mapping = 2*sigmoid(1e-4*h_post + post_beta)
        float pre[4], post[4];
        #pragma unroll
        for (int n = 0; n < 4; n++) {
            pre[n]  = 1.f / (1.f + expf(-(1e-4f * h[16 + n] + pb[n])));
            post[n] = 2.f / (1.f + expf(-(1e-4f * h[20 + n] + qb[n])));
        }
        // Sinkhorn on Z = (1e-4*h_res + res_beta[b]) / 0.05
        float Z[16];
        #pragma unroll
        for (int a = 0; a < 4; a++)
            #pragma unroll
            for (int b = 0; b < 4; b++)
                Z[a * 4 + b] = (1e-4f * h[a * 4 + b] + rb[b]) * 20.0f;
        float u[4] = {0.f, 0.f, 0.f, 0.f};
        float v[4] = {0.f, 0.f, 0.f, 0.f};
        for (int it = 0; it < 20; it++) {
            #pragma unroll
            for (int a = 0; a < 4; a++)
                u[a] = -lse4(Z[a*4+0] + v[0], Z[a*4+1] + v[1], Z[a*4+2] + v[2], Z[a*4+3] + v[3]);
            #pragma unroll
            for (int b = 0; b < 4; b++)
                v[b] = -lse4(Z[0*4+b] + u[0], Z[1*4+b] + u[1], Z[2*4+b] + u[2], Z[3*4+b] + u[3]);
        }
        #pragma unroll
        for (int a = 0; a < 4; a++)
            #pragma unroll
            for (int b = 0; b < 4; b++)
                g_maps[a * 4 + b] = expf(Z[a * 4 + b] + u[a] + v[b]);
        #pragma unroll
        for (int n = 0; n < 4; n++) { g_maps[16 + n] = pre[n]; g_maps[20 + n] = post[n]; }
    }
}

// ---------------------------------------------------------------------------
// Kernel 3: outputs. out = [res_out (K,B,S,D) | post_out (K,B,S,D)], fp32.
// ---------------------------------------------------------------------------
__global__ __launch_bounds__(256) void k_out(
    const float* __restrict__ x,
    const float* __restrict__ w,
    float* __restrict__ out)
{
    __shared__ float mp[24];
    if (threadIdx.x < 24) mp[threadIdx.x] = g_maps[threadIdx.x];
    __syncthreads();

    const int j  = blockIdx.x * 256 + threadIdx.x;   // float4 index in (b,s,d), 0..524287
    const int bs = j >> 8;                           // (b,s) row index, 0..2047

    const float4* x4 = reinterpret_cast<const float4*>(x);
    float4 wv = reinterpret_cast<const float4*>(w)[j & 255];

    float4 xn[4];
    #pragma unroll
    for (int n = 0; n < 4; n++) {
        float4 v = x4[(size_t)n * (BSD / 4) + j];
        float inv = g_inv[n * BSROWS + bs];
        xn[n].x = v.x * inv * wv.x;
        xn[n].y = v.y * inv * wv.y;
        xn[n].z = v.z * inv * wv.z;
        xn[n].w = v.w * inv * wv.w;
    }

    float4 L = make_float4(0.f, 0.f, 0.f, 0.f);
    #pragma unroll
    for (int n = 0; n < 4; n++) {
        float p = mp[16 + n];
        L.x += xn[n].x * p; L.y += xn[n].y * p; L.z += xn[n].z * p; L.w += xn[n].w * p;
    }

    float4* o4 = reinterpret_cast<float4*>(out);
    // res_out[m] = sum_n xn[n] * res_map[n][m]
    #pragma unroll
    for (int m = 0; m < 4; m++) {
        float4 r = make_float4(0.f, 0.f, 0.f, 0.f);
        #pragma unroll
        for (int n = 0; n < 4; n++) {
            float c = mp[n * 4 + m];
            r.x += xn[n].x * c; r.y += xn[n].y * c; r.z += xn[n].z * c; r.w += xn[n].w * c;
        }
        o4[(size_t)m * (BSD / 4) + j] = r;
    }
    // post_out[n] = layer * post_map[n]
    #pragma unroll
    for (int n = 0; n < 4; n++) {
        float c = mp[20 + n];
        float4 p = make_float4(L.x * c, L.y * c, L.z * c, L.w * c);
        o4[(size_t)(NBSD / 4) + (size_t)n * (BSD / 4) + j] = p;
    }
}

// ---------------------------------------------------------------------------
extern "C" void kernel_launch(void* const* d_in, const int* in_sizes, int n_in,
                              void* d_out, int out_size)
{
    const float* x  = (const float*)d_in[0];   // (K,B,S,D)
    const float* w  = (const float*)d_in[1];   // (D,)
    const float* ra = (const float*)d_in[2];   // (K,B,S,D,16)
    const float* pa = (const float*)d_in[3];   // (K,B,S,D,4)
    const float* qa = (const float*)d_in[4];   // (K,B,S,D,4)
    const float* rb = (const float*)d_in[5];   // (K,)
    const float* pb = (const float*)d_in[6];   // (K,)
    const float* qb = (const float*)d_in[7];   // (K,)
    float* out = (float*)d_out;

    k_reduce<<<NROWS, 256>>>(x, w, ra, pa, qa);
    k_final<<<1, 256>>>(rb, pb, qb);
    k_out<<<(BSD / 4) / 256, 256>>>(x, w, out);
}

// round 3
// speedup vs baseline: 1.2863x; 1.2863x over previous
#include <cuda_runtime.h>
#include <math.h>

// Problem constants
#define KK 4
#define BB 2
#define SS 1024
#define DD 1024
#define NROWS (KK*BB*SS)      // 8192 rows of length D
#define BSROWS (BB*SS)        // 2048
#define BSD (BB*SS*DD)        // 2,097,152
#define NBSD (KK*BSD)         // 8,388,608
#define HS_BLOCKS 32          // second-level reduction blocks

// Scratch (allocation-free: device globals)
__device__ float g_partial[NROWS * 24];      // per-row partial reductions
__device__ float g_partial2[HS_BLOCKS * 24]; // second-level partials
__device__ float g_inv[NROWS];               // per-row rsqrt(mean(x^2)+eps)
__device__ float g_maps[24];                 // [0..15] res_map[n*4+m], [16..19] pre, [20..23] post

// ---------------------------------------------------------------------------
// Kernel 1: per-row RMS norm + the big alpha reductions.
// One block = one (n,b,s) row. All alpha accesses are contiguous streaming.
// ---------------------------------------------------------------------------
__global__ __launch_bounds__(256) void k_reduce(
    const float* __restrict__ x,
    const float* __restrict__ w,
    const float* __restrict__ ra,   // res_alpha  [row][D][16]
    const float* __restrict__ pa,   // pre_alpha  [row][D][4]
    const float* __restrict__ qa)   // post_alpha [row][D][4]
{
    __shared__ float xn_sh[DD];
    __shared__ float ssw[8];
    __shared__ float red[8 * 24];

    const int row = blockIdx.x;
    const int t   = threadIdx.x;
    const int wid = t >> 5;
    const int ln  = t & 31;

    // ---- RMS norm: each thread owns 4 consecutive d's ----
    const float4* x4 = reinterpret_cast<const float4*>(x) + (size_t)row * (DD / 4);
    float4 xv = x4[t];
    float ss = xv.x*xv.x + xv.y*xv.y + xv.z*xv.z + xv.w*xv.w;
    #pragma unroll
    for (int o = 16; o; o >>= 1) ss += __shfl_xor_sync(0xffffffffu, ss, o);
    if (ln == 0) ssw[wid] = ss;
    __syncthreads();
    float tot = ssw[0] + ssw[1] + ssw[2] + ssw[3] + ssw[4] + ssw[5] + ssw[6] + ssw[7];
    const float inv = rsqrtf(tot * (1.0f / (float)DD) + 1e-6f);
    if (t == 0) g_inv[row] = inv;

    float4 wv = reinterpret_cast<const float4*>(w)[t];
    float4 xnv;
    xnv.x = xv.x * inv * wv.x;
    xnv.y = xv.y * inv * wv.y;
    xnv.z = xv.z * inv * wv.z;
    xnv.w = xv.w * inv * wv.w;
    reinterpret_cast<float4*>(xn_sh)[t] = xnv;
    __syncthreads();

    // ---- res_alpha: row is [D][16] = 16384 floats = 4096 float4s ----
    // float4 index j covers d = j>>2, m = (j&3)*4 .. +3 ; j&3 == t&3 (constant per thread)
    const float4* ra4 = reinterpret_cast<const float4*>(ra) + (size_t)row * (DD * 16 / 4);
    float4 accr = make_float4(0.f, 0.f, 0.f, 0.f);
    #pragma unroll
    for (int i = 0; i < 16; i++) {
        const int j = i * 256 + t;
        float4 v = __ldcs(&ra4[j]);                 // single-use stream: evict-first
        float xs = xn_sh[j >> 2];
        accr.x += xs * v.x; accr.y += xs * v.y; accr.z += xs * v.z; accr.w += xs * v.w;
    }

    // ---- pre_alpha: row is [D][4] = 1024 float4s; j covers d=j, m=0..3 ----
    const float4* pa4 = reinterpret_cast<const float4*>(pa) + (size_t)row * DD;
    const float4* qa4 = reinterpret_cast<const float4*>(qa) + (size_t)row * DD;
    float4 accp = make_float4(0.f, 0.f, 0.f, 0.f);
    float4 accq = make_float4(0.f, 0.f, 0.f, 0.f);
    #pragma unroll
    for (int i = 0; i < 4; i++) {
        const int j = i * 256 + t;
        float xs = xn_sh[j];
        float4 v = __ldcs(&pa4[j]);
        accp.x += xs * v.x; accp.y += xs * v.y; accp.z += xs * v.z; accp.w += xs * v.w;
        float4 u = __ldcs(&qa4[j]);
        accq.x += xs * u.x; accq.y += xs * u.y; accq.z += xs * u.z; accq.w += xs * u.w;
    }

    // ---- block reductions ----
    #pragma unroll
    for (int o = 16; o >= 4; o >>= 1) {
        accr.x += __shfl_xor_sync(0xffffffffu, accr.x, o);
        accr.y += __shfl_xor_sync(0xffffffffu, accr.y, o);
        accr.z += __shfl_xor_sync(0xffffffffu, accr.z, o);
        accr.w += __shfl_xor_sync(0xffffffffu, accr.w, o);
    }
    #pragma unroll
    for (int o = 16; o; o >>= 1) {
        accp.x += __shfl_xor_sync(0xffffffffu, accp.x, o);
        accp.y += __shfl_xor_sync(0xffffffffu, accp.y, o);
        accp.z += __shfl_xor_sync(0xffffffffu, accp.z, o);
        accp.w += __shfl_xor_sync(0xffffffffu, accp.w, o);
        accq.x += __shfl_xor_sync(0xffffffffu, accq.x, o);
        accq.y += __shfl_xor_sync(0xffffffffu, accq.y, o);
        accq.z += __shfl_xor_sync(0xffffffffu, accq.z, o);
        accq.w += __shfl_xor_sync(0xffffffffu, accq.w, o);
    }

    if (ln < 4) {   // lane ln holds res group g=ln -> m = ln*4 + c
        red[wid * 24 + ln * 4 + 0] = accr.x;
        red[wid * 24 + ln * 4 + 1] = accr.y;
        red[wid * 24 + ln * 4 + 2] = accr.z;
        red[wid * 24 + ln * 4 + 3] = accr.w;
    }
    if (ln == 0) {
        red[wid * 24 + 16] = accp.x; red[wid * 24 + 17] = accp.y;
        red[wid * 24 + 18] = accp.z; red[wid * 24 + 19] = accp.w;
        red[wid * 24 + 20] = accq.x; red[wid * 24 + 21] = accq.y;
        red[wid * 24 + 22] = accq.z; red[wid * 24 + 23] = accq.w;
    }
    __syncthreads();
    if (t < 24) {
        float s = 0.f;
        #pragma unroll
        for (int wv_ = 0; wv_ < 8; wv_++) s += red[wv_ * 24 + t];
        g_partial[(size_t)row * 24 + t] = s;
    }
}

// ---------------------------------------------------------------------------
// Kernel 2: second-level reduction of per-row partials. 32 blocks x 256 thr,
// each block reduces 256 contiguous rows (coalesced 96B per thread).
// ---------------------------------------------------------------------------
__global__ __launch_bounds__(256) void k_hsum()
{
    const int t   = threadIdx.x;
    const int wid = t >> 5;
    const int ln  = t & 31;
    const int row = blockIdx.x * 256 + t;

    float acc[24];
    const float* p = g_partial + (size_t)row * 24;
    #pragma unroll
    for (int v = 0; v < 24; v++) acc[v] = p[v];

    #pragma unroll
    for (int v = 0; v < 24; v++) {
        #pragma unroll
        for (int o = 16; o; o >>= 1) acc[v] += __shfl_xor_sync(0xffffffffu, acc[v], o);
    }
    __shared__ float sh[8][24];
    if (ln == 0) {
        #pragma unroll
        for (int v = 0; v < 24; v++) sh[wid][v] = acc[v];
    }
    __syncthreads();
    if (t < 24) {
        float s = 0.f;
        #pragma unroll
        for (int wv_ = 0; wv_ < 8; wv_++) s += sh[wv_][t];
        g_partial2[blockIdx.x * 24 + t] = s;
    }
}

// ---------------------------------------------------------------------------
// Kernel 3: final 24-way sum + sigmoid maps + warp-parallel 4x4 Sinkhorn.
// Lane = a*4+b owns one Z entry; row-lse via shfl_xor 1,2; col via 4,8.
// ---------------------------------------------------------------------------
__global__ __launch_bounds__(32) void k_maps(
    const float* __restrict__ rb,
    const float* __restrict__ pb,
    const float* __restrict__ qb)
{
    const int ln = threadIdx.x;

    // Sum the 32 second-level partials for component ln (lanes 24..31 idle-safe)
    float h = 0.f;
    if (ln < 24) {
        #pragma unroll
        for (int b = 0; b < HS_BLOCKS; b++) h += g_partial2[b * 24 + ln];
    }

    // pre/post sigmoid maps (lanes 16..23)
    if (ln >= 16 && ln < 20) {
        float v = 1.f / (1.f + __expf(-(1e-4f * h + pb[ln - 16])));
        g_maps[ln] = v;
    }
    if (ln >= 20 && ln < 24) {
        float v = 2.f / (1.f + __expf(-(1e-4f * h + qb[ln - 20])));
        g_maps[ln] = v;
    }

    // Sinkhorn on lanes 0..15 (a = ln>>2, b = ln&3). All lanes run the shfl
    // network; lanes >=16 compute garbage that never mixes into lanes <16
    // (xor offsets 1,2,4,8 keep lane<16 within lane<16).
    const int bcol = ln & 3;
    float Z = (ln < 16) ? (1e-4f * h + rb[bcol]) * 20.0f : 0.f;
    float u = 0.f, v = 0.f;
    #pragma unroll 1
    for (int it = 0; it < 20; it++) {
        // row logsumexp over the quad (b varies: xor 1,2)
        float tr = Z + v;
        float m = fmaxf(tr, __shfl_xor_sync(0xffffffffu, tr, 1));
        m = fmaxf(m, __shfl_xor_sync(0xffffffffu, m, 2));
        float e = __expf(tr - m);
        float s = e + __shfl_xor_sync(0xffffffffu, e, 1);
        s += __shfl_xor_sync(0xffffffffu, s, 2);
        u = -(m + __logf(s));
        // col logsumexp (a varies: xor 4,8)
        float tc = Z + u;
        float m2 = fmaxf(tc, __shfl_xor_sync(0xffffffffu, tc, 4));
        m2 = fmaxf(m2, __shfl_xor_sync(0xffffffffu, m2, 8));
        float e2 = __expf(tc - m2);
        float s2 = e2 + __shfl_xor_sync(0xffffffffu, e2, 4);
        s2 += __shfl_xor_sync(0xffffffffu, s2, 8);
        v = -(m2 + __logf(s2));
    }
    if (ln < 16) g_maps[ln] = __expf(Z + u + v);
}

// ---------------------------------------------------------------------------
// Kernel 4: outputs. out = [res_out (K,B,S,D) | post_out (K,B,S,D)], fp32.
// ---------------------------------------------------------------------------
__global__ __launch_bounds__(256) void k_out(
    const float* __restrict__ x,
    const float* __restrict__ w,
    float* __restrict__ out)
{
    __shared__ float mp[24];
    if (threadIdx.x < 24) mp[threadIdx.x] = g_maps[threadIdx.x];
    __syncthreads();

    const int j  = blockIdx.x * 256 + threadIdx.x;   // float4 index in (b,s,d)
    const int bs = j >> 8;                           // (b,s) row index

    const float4* x4 = reinterpret_cast<const float4*>(x);
    float4 wv = reinterpret_cast<const float4*>(w)[j & 255];

    float4 xn[4];
    #pragma unroll
    for (int n = 0; n < 4; n++) {
        float4 v = x4[(size_t)n * (BSD / 4) + j];
        float inv = g_inv[n * BSROWS + bs];
        xn[n].x = v.x * inv * wv.x;
        xn[n].y = v.y * inv * wv.y;
        xn[n].z = v.z * inv * wv.z;
        xn[n].w = v.w * inv * wv.w;
    }

    float4 L = make_float4(0.f, 0.f, 0.f, 0.f);
    #pragma unroll
    for (int n = 0; n < 4; n++) {
        float p = mp[16 + n];
        L.x += xn[n].x * p; L.y += xn[n].y * p; L.z += xn[n].z * p; L.w += xn[n].w * p;
    }

    float4* o4 = reinterpret_cast<float4*>(out);
    // res_out[m] = sum_n xn[n] * res_map[n][m]
    #pragma unroll
    for (int m = 0; m < 4; m++) {
        float4 r = make_float4(0.f, 0.f, 0.f, 0.f);
        #pragma unroll
        for (int n = 0; n < 4; n++) {
            float c = mp[n * 4 + m];
            r.x += xn[n].x * c; r.y += xn[n].y * c; r.z += xn[n].z * c; r.w += xn[n].w * c;
        }
        __stcs(&o4[(size_t)m * (BSD / 4) + j], r);
    }
    // post_out[n] = layer * post_map[n]
    #pragma unroll
    for (int n = 0; n < 4; n++) {
        float c = mp[20 + n];
        float4 p = make_float4(L.x * c, L.y * c, L.z * c, L.w * c);
        __stcs(&o4[(size_t)(NBSD / 4) + (size_t)n * (BSD / 4) + j], p);
    }
}

// ---------------------------------------------------------------------------
extern "C" void kernel_launch(void* const* d_in, const int* in_sizes, int n_in,
                              void* d_out, int out_size)
{
    const float* x  = (const float*)d_in[0];   // (K,B,S,D)
    const float* w  = (const float*)d_in[1];   // (D,)
    const float* ra = (const float*)d_in[2];   // (K,B,S,D,16)
    const float* pa = (const float*)d_in[3];   // (K,B,S,D,4)
    const float* qa = (const float*)d_in[4];   // (K,B,S,D,4)
    const float* rb = (const float*)d_in[5];   // (K,)
    const float* pb = (const float*)d_in[6];   // (K,)
    const float* qb = (const float*)d_in[7];   // (K,)
    float* out = (float*)d_out;

    k_reduce<<<NROWS, 256>>>(x, w, ra, pa, qa);
    k_hsum<<<HS_BLOCKS, 256>>>();
    k_maps<<<1, 32>>>(rb, pb, qb);
    k_out<<<(BSD / 4) / 256, 256>>>(x, w, out);
}